// round 1
// baseline (speedup 1.0000x reference)
#include <cuda_runtime.h>
#include <math.h>
#include <stdint.h>

#define NA    9216      // 96*96
#define CDIM  1280
#define HW48  2304      // 48*48
#define NTILES 144      // 9216/64
#define SSPLIT 64

// ---------------- scratch (device globals; no allocation allowed) ----------
__device__ float g_tmp[CDIM * 64 * 96];       // horizontal-resize temp
__device__ float g_ref96[CDIM * NA];          // (C, N) c-major
__device__ float g_feat96[CDIM * NA];         // (C, N) c-major
__device__ float g_E[(size_t)NA * NA];        // exp(sim) scratch, 340MB
__device__ float g_Zpart[NTILES * NA];        // per-Ntile row-sum partials
__device__ float g_invZ[NA];
__device__ float g_partial[SSPLIT * NA];      // column-reduce partials
__device__ float g_x1[HW48];
__device__ float g_out48[HW48];
__device__ int   g_active[NA];
__device__ int   g_count;
__device__ unsigned char g_flag[NA];

// ---------------- mask + compaction ----------------------------------------
__global__ void k_flag(const float* __restrict__ guid) {
    int i = blockIdx.x * blockDim.x + threadIdx.x;
    if (i >= NA) return;
    int by = i / 96, bx = i % 96;
    const float* p = guid + (by * 8) * 768 + bx * 8;
    bool all = true;
    #pragma unroll
    for (int dy = 0; dy < 8; dy++)
        #pragma unroll
        for (int dx = 0; dx < 8; dx++)
            all = all && (p[dy * 768 + dx] > 0.5f);
    g_flag[i] = all ? 1 : 0;
}

__global__ void k_compact() {   // 1 block, 256 threads (deterministic scan)
    __shared__ int s_cnt[256];
    __shared__ int s_off[256];
    int t = threadIdx.x;
    int c = 0;
    for (int k = 0; k < 36; k++) c += g_flag[t * 36 + k];
    s_cnt[t] = c;
    __syncthreads();
    if (t == 0) {
        int acc = 0;
        for (int i = 0; i < 256; i++) { s_off[i] = acc; acc += s_cnt[i]; }
        g_count = acc;
    }
    __syncthreads();
    int off = s_off[t];
    for (int k = 0; k < 36; k++) {
        int i = t * 36 + k;
        if (g_flag[i]) g_active[off++] = i;
    }
}

// ---------------- cubic resize (jax.image.resize semantics) ----------------
__device__ __forceinline__ float keys_cubic(float x) {
    x = fabsf(x);
    if (x < 1.f)  return ((1.5f * x - 2.5f) * x) * x + 1.f;
    if (x < 2.f)  return ((-0.5f * x + 2.5f) * x - 4.f) * x + 2.f;
    return 0.f;
}

// half-pixel sampling + edge renormalization (matches jax weight matrix)
__device__ __forceinline__ void cubic_w(int o, int insz, int outsz,
                                        int idx[4], float w[4]) {
    float s = (o + 0.5f) * ((float)insz / (float)outsz) - 0.5f;
    int fl = (int)floorf(s);
    float tot = 0.f;
    #pragma unroll
    for (int t = 0; t < 4; t++) {
        int ii = fl - 1 + t;
        float ww = (ii >= 0 && ii < insz) ? keys_cubic(s - (float)ii) : 0.f;
        idx[t] = min(max(ii, 0), insz - 1);
        w[t] = ww;
        tot += ww;
    }
    float inv = 1.f / tot;
    #pragma unroll
    for (int t = 0; t < 4; t++) w[t] *= inv;
}

__global__ void k_resize_h(const float* __restrict__ in) {
    // in: (1280,64,64) -> g_tmp: (1280,64,96)
    int idx = blockIdx.x * blockDim.x + threadIdx.x;
    if (idx >= CDIM * 64 * 96) return;
    int xo = idx % 96;
    int r  = idx / 96;           // c*64 + y
    int ti[4]; float w[4];
    cubic_w(xo, 64, 96, ti, w);
    const float* p = in + r * 64;
    g_tmp[idx] = w[0]*p[ti[0]] + w[1]*p[ti[1]] + w[2]*p[ti[2]] + w[3]*p[ti[3]];
}

__global__ void k_resize_v(int which) {
    // g_tmp (1280,64,96) -> (which? g_ref96 : g_feat96)[c*9216 + yo*96 + xo]
    int idx = blockIdx.x * blockDim.x + threadIdx.x;
    if (idx >= CDIM * NA) return;
    int xo = idx % 96;
    int yo = (idx / 96) % 96;
    int c  = idx / NA;
    int ti[4]; float w[4];
    cubic_w(yo, 64, 96, ti, w);
    const float* p = g_tmp + c * (64 * 96) + xo;
    float v = w[0]*p[ti[0]*96] + w[1]*p[ti[1]*96] + w[2]*p[ti[2]*96] + w[3]*p[ti[3]*96];
    if (which) g_ref96[idx] = v; else g_feat96[idx] = v;
}

// ---------------- sim GEMM + exp + deterministic row sums -------------------
#define BM 64
#define BN 64
#define BK 32

__global__ __launch_bounds__(256) void k_gemm_exp() {
    int count = g_count;
    int m0 = blockIdx.y * BM;
    if (m0 >= count) return;
    int n0 = blockIdx.x * BN;

    __shared__ float As[BK][BM];
    __shared__ float Bs[BK][BN];
    __shared__ int   acts[BM];

    int tid = threadIdx.x;
    if (tid < BM) {
        int gm = m0 + tid;
        acts[tid] = (gm < count) ? g_active[gm] : -1;
    }
    __syncthreads();

    int tx = tid & 15, ty = tid >> 4;
    int mload = tid & 63;
    int kbase = tid >> 6;            // 0..3
    int colA  = acts[mload];

    float acc[4][4] = {};

    for (int k0 = 0; k0 < CDIM; k0 += BK) {
        #pragma unroll
        for (int it = 0; it < 8; it++) {
            int kk = kbase + it * 4;
            As[kk][mload] = (colA >= 0) ? g_ref96[(k0 + kk) * NA + colA] : 0.f;
            Bs[kk][mload] = g_feat96[(k0 + kk) * NA + n0 + mload];
        }
        __syncthreads();
        #pragma unroll
        for (int kk = 0; kk < BK; kk++) {
            float4 a = *(const float4*)&As[kk][ty * 4];
            float4 b = *(const float4*)&Bs[kk][tx * 4];
            acc[0][0] += a.x*b.x; acc[0][1] += a.x*b.y; acc[0][2] += a.x*b.z; acc[0][3] += a.x*b.w;
            acc[1][0] += a.y*b.x; acc[1][1] += a.y*b.y; acc[1][2] += a.y*b.z; acc[1][3] += a.y*b.w;
            acc[2][0] += a.z*b.x; acc[2][1] += a.z*b.y; acc[2][2] += a.z*b.z; acc[2][3] += a.z*b.w;
            acc[3][0] += a.w*b.x; acc[3][1] += a.w*b.y; acc[3][2] += a.w*b.z; acc[3][3] += a.w*b.w;
        }
        __syncthreads();
    }

    // epilogue: e = exp(sim/1000); store E; deterministic per-tile row sums
    #pragma unroll
    for (int i = 0; i < 4; i++) {
        int row = m0 + ty * 4 + i;
        float e0 = __expf(acc[i][0] * 1e-3f);
        float e1 = __expf(acc[i][1] * 1e-3f);
        float e2 = __expf(acc[i][2] * 1e-3f);
        float e3 = __expf(acc[i][3] * 1e-3f);
        bool valid = (row < count);
        if (valid) {
            float4 ev = make_float4(e0, e1, e2, e3);
            *(float4*)&g_E[(size_t)row * NA + n0 + tx * 4] = ev;
        }
        float rs = e0 + e1 + e2 + e3;
        // reduce across the 16 lanes sharing this row (tx group within half-warp)
        #pragma unroll
        for (int off = 8; off; off >>= 1)
            rs += __shfl_xor_sync(0xffffffffu, rs, off);
        if (tx == 0 && valid)
            g_Zpart[blockIdx.x * NA + row] = rs;
    }
}

__global__ void k_invz() {
    int i = blockIdx.x * blockDim.x + threadIdx.x;
    if (i >= NA || i >= g_count) return;
    float z = 0.f;
    for (int t = 0; t < NTILES; t++) z += g_Zpart[t * NA + i];
    g_invZ[i] = 1.f / z;
}

// ---------------- column reduction: attn_out_j = sum_i E[i,j]*invZ[i] ------
__global__ void k_colreduce() {
    int j = blockIdx.x * 256 + threadIdx.x;     // 36 x-blocks
    int s = blockIdx.y;                         // 64 row-splits
    int count = g_count;
    float acc = 0.f;
    for (int ci = s; ci < count; ci += SSPLIT)
        acc += g_E[(size_t)ci * NA + j] * g_invZ[ci];
    g_partial[s * NA + j] = acc;
}

__global__ void k_colfinish(float* __restrict__ maskout) {
    int j = blockIdx.x * blockDim.x + threadIdx.x;
    if (j >= NA) return;
    float a = 0.f;
    for (int s = 0; s < SSPLIT; s++) a += g_partial[s * NA + j];
    maskout[j] = a;
}

// ---------------- bilinear align_corners 96 -> 48 ---------------------------
__global__ void k_x1(const float* __restrict__ mask) {
    int k = blockIdx.x * blockDim.x + threadIdx.x;
    if (k >= HW48) return;
    int yo = k / 48, xo = k % 48;
    const float step = 95.f / 47.f;
    float ys = yo * step, xs = xo * step;
    int y0 = (int)floorf(ys), x0 = (int)floorf(xs);
    int y1 = min(y0 + 1, 95), x1i = min(x0 + 1, 95);
    float wy = ys - (float)y0, wx = xs - (float)x0;
    float a = mask[y0 * 96 + x0],  b = mask[y0 * 96 + x1i];
    float c = mask[y1 * 96 + x0],  d = mask[y1 * 96 + x1i];
    g_x1[k] = (a * (1.f - wx) + b * wx) * (1.f - wy) + (c * (1.f - wx) + d * wx) * wy;
}

// ---------------- out48[j] = sum_k x1[k] * A[j,k] ---------------------------
__global__ void k_attn(const float* __restrict__ A) {
    __shared__ float red[256];
    int j = blockIdx.x;
    int t = threadIdx.x;
    float acc = 0.f;
    const float* row = A + (size_t)j * HW48;
    for (int k = t; k < HW48; k += 256) acc += g_x1[k] * row[k];
    red[t] = acc;
    __syncthreads();
    for (int s = 128; s; s >>= 1) {
        if (t < s) red[t] += red[t + s];
        __syncthreads();
    }
    if (t == 0) g_out48[j] = red[0];
}

// ---------------- bilinear (half-pixel, clamp) 48 -> 768 --------------------
__global__ void k_trimap(float* __restrict__ out) {
    int idx = blockIdx.x * blockDim.x + threadIdx.x;
    if (idx >= 768 * 768) return;
    int ox = idx % 768, oy = idx / 768;
    float sx = (ox + 0.5f) * (1.f / 16.f) - 0.5f;
    float sy = (oy + 0.5f) * (1.f / 16.f) - 0.5f;
    int x0 = (int)floorf(sx), y0 = (int)floorf(sy);
    float wx = sx - (float)x0, wy = sy - (float)y0;
    int x0c = max(x0, 0), x1c = min(x0 + 1, 47);
    int y0c = max(y0, 0), y1c = min(y0 + 1, 47);
    float a = g_out48[y0c * 48 + x0c], b = g_out48[y0c * 48 + x1c];
    float c = g_out48[y1c * 48 + x0c], d = g_out48[y1c * 48 + x1c];
    out[idx] = (a * (1.f - wx) + b * wx) * (1.f - wy) + (c * (1.f - wx) + d * wx) * wy;
}

// ---------------- launch ----------------------------------------------------
extern "C" void kernel_launch(void* const* d_in, const int* in_sizes, int n_in,
                              void* d_out, int out_size) {
    (void)in_sizes; (void)n_in; (void)out_size;
    const float* ref_img = (const float*)d_in[0];
    const float* ft_cor  = (const float*)d_in[1];
    const float* attnA   = (const float*)d_in[2];
    const float* ft_mat  = (const float*)d_in[3];
    const float* guid    = (const float*)d_in[4];

    float* out     = (float*)d_out;
    float* trimap  = out;                       // 768*768
    float* matting = out + 768 * 768;           // 1280*64*64
    float* maskout = matting + 1280 * 64 * 64;  // 9216

    k_flag<<<36, 256>>>(guid);
    k_compact<<<1, 256>>>();

    int nrh = (CDIM * 64 * 96 + 255) / 256;
    int nrv = (CDIM * NA + 255) / 256;
    k_resize_h<<<nrh, 256>>>(ft_cor);
    k_resize_v<<<nrv, 256>>>(0);                // -> g_feat96
    k_resize_h<<<nrh, 256>>>(ref_img);
    k_resize_v<<<nrv, 256>>>(1);                // -> g_ref96

    k_gemm_exp<<<dim3(NTILES, NTILES), 256>>>();
    k_invz<<<36, 256>>>();
    k_colreduce<<<dim3(36, SSPLIT), 256>>>();
    k_colfinish<<<36, 256>>>(maskout);

    k_x1<<<9, 256>>>(maskout);
    k_attn<<<HW48, 256>>>(attnA);
    k_trimap<<<(768 * 768 + 255) / 256, 256>>>(trimap);

    cudaMemcpyAsync(matting, ft_mat, (size_t)1280 * 64 * 64 * sizeof(float),
                    cudaMemcpyDeviceToDevice);
}

// round 3
// speedup vs baseline: 5.7438x; 5.7438x over previous
#include <cuda_runtime.h>
#include <cuda_bf16.h>
#include <math.h>
#include <stdint.h>

#define NA     9216      // 96*96
#define CDIM   1280
#define HW48   2304      // 48*48
#define MT     72        // 9216/128 tiles per GEMM dim
#define NIT    40        // 1280/32 K-iterations
#define SSPLIT 64

// ---------------- scratch (device globals; no allocation allowed) ----------
__device__ float g_tmp[CDIM * 64 * 96];              // horizontal-resize temp
__device__ __nv_bfloat16 g_refb[(size_t)NA * CDIM];  // (N, C) row-major bf16
__device__ __nv_bfloat16 g_featb[(size_t)NA * CDIM];
__device__ __nv_bfloat16 g_E[(size_t)NA * NA];       // exp(sim), bf16, 170MB
__device__ float g_Zpart[MT * NA];
__device__ float g_invZ[NA];
__device__ float g_partial[SSPLIT * NA];
__device__ float g_x1[HW48];
__device__ float g_out48[HW48];
__device__ int   g_active[NA];
__device__ int   g_count;
__device__ unsigned char g_flag[NA];
__device__ int4   g_it4[96];
__device__ float4 g_wt4[96];

// ---------------- PTX helpers (baseline sm_80+ only; NO tcgen05) -----------
__device__ __forceinline__ uint32_t smem_u32(const void* p) {
    uint32_t a;
    asm("{ .reg .u64 t; cvta.to.shared.u64 t, %1; cvt.u32.u64 %0, t; }"
        : "=r"(a) : "l"(p));
    return a;
}
__device__ __forceinline__ void cpa16(uint32_t dst, const void* src, int sz) {
    asm volatile("cp.async.cg.shared.global [%0], [%1], 16, %2;"
                 :: "r"(dst), "l"(src), "r"(sz) : "memory");
}
#define CP_COMMIT() asm volatile("cp.async.commit_group;" ::: "memory")
#define CP_WAIT(n)  asm volatile("cp.async.wait_group %0;" :: "n"(n) : "memory")

__device__ __forceinline__ void ldsm4(uint32_t* r, uint32_t addr) {
    asm volatile("ldmatrix.sync.aligned.m8n8.x4.shared.b16 {%0,%1,%2,%3}, [%4];"
                 : "=r"(r[0]), "=r"(r[1]), "=r"(r[2]), "=r"(r[3]) : "r"(addr));
}
__device__ __forceinline__ void mma16816(float* d, const uint32_t* a,
                                         const uint32_t* b) {
    asm volatile(
        "mma.sync.aligned.m16n8k16.row.col.f32.bf16.bf16.f32 "
        "{%0,%1,%2,%3},{%4,%5,%6,%7},{%8,%9},{%0,%1,%2,%3};"
        : "+f"(d[0]), "+f"(d[1]), "+f"(d[2]), "+f"(d[3])
        : "r"(a[0]), "r"(a[1]), "r"(a[2]), "r"(a[3]), "r"(b[0]), "r"(b[1]));
}

// ---------------- mask + compaction ----------------------------------------
__global__ void k_flag(const float* __restrict__ guid) {
    int i = blockIdx.x * blockDim.x + threadIdx.x;
    if (i >= NA) return;
    int by = i / 96, bx = i % 96;
    const float* p = guid + (by * 8) * 768 + bx * 8;
    bool all = true;
    #pragma unroll
    for (int dy = 0; dy < 8; dy++)
        #pragma unroll
        for (int dx = 0; dx < 8; dx++)
            all = all && (p[dy * 768 + dx] > 0.5f);
    g_flag[i] = all ? 1 : 0;
}

__global__ void k_compact() {
    __shared__ int s_cnt[256];
    __shared__ int s_off[256];
    int t = threadIdx.x;
    int c = 0;
    for (int k = 0; k < 36; k++) c += g_flag[t * 36 + k];
    s_cnt[t] = c;
    __syncthreads();
    if (t == 0) {
        int acc = 0;
        for (int i = 0; i < 256; i++) { s_off[i] = acc; acc += s_cnt[i]; }
        g_count = acc;
    }
    __syncthreads();
    int off = s_off[t];
    for (int k = 0; k < 36; k++) {
        int i = t * 36 + k;
        if (g_flag[i]) g_active[off++] = i;
    }
}

// ---------------- cubic weight tables ---------------------------------------
__device__ __forceinline__ float keys_cubic(float x) {
    x = fabsf(x);
    if (x < 1.f)  return ((1.5f * x - 2.5f) * x) * x + 1.f;
    if (x < 2.f)  return ((-0.5f * x + 2.5f) * x - 4.f) * x + 2.f;
    return 0.f;
}

__global__ void k_weights() {
    int o = threadIdx.x;
    if (o >= 96) return;
    float s = (o + 0.5f) * (64.f / 96.f) - 0.5f;
    int fl = (int)floorf(s);
    int idx[4]; float w[4]; float tot = 0.f;
    #pragma unroll
    for (int t = 0; t < 4; t++) {
        int ii = fl - 1 + t;
        float ww = (ii >= 0 && ii < 64) ? keys_cubic(s - (float)ii) : 0.f;
        idx[t] = min(max(ii, 0), 63);
        w[t] = ww;
        tot += ww;
    }
    float inv = 1.f / tot;
    g_it4[o] = make_int4(idx[0], idx[1], idx[2], idx[3]);
    g_wt4[o] = make_float4(w[0]*inv, w[1]*inv, w[2]*inv, w[3]*inv);
}

// horizontal cubic: (1280,64,64) -> g_tmp (1280,64,96)
__global__ void k_resize_h(const float* __restrict__ in) {
    int idx = blockIdx.x * blockDim.x + threadIdx.x;
    if (idx >= CDIM * 64 * 96) return;
    int xo = idx % 96;
    int r  = idx / 96;
    int4  ti = g_it4[xo];
    float4 w = g_wt4[xo];
    const float* p = in + r * 64;
    g_tmp[idx] = w.x*p[ti.x] + w.y*p[ti.y] + w.z*p[ti.z] + w.w*p[ti.w];
}

// vertical cubic + transpose to (N, C) bf16
__global__ void k_resize_vt(int which) {
    __shared__ float t[32][33];
    int n = blockIdx.x * 32 + threadIdx.x;
    int yo = n / 96, xo = n % 96;
    int4  ti = g_it4[yo];
    float4 w = g_wt4[yo];
    #pragma unroll
    for (int i = 0; i < 4; i++) {
        int c = blockIdx.y * 32 + threadIdx.y + i * 8;
        const float* p = g_tmp + c * (64 * 96) + xo;
        t[threadIdx.y + i * 8][threadIdx.x] =
            w.x*p[ti.x*96] + w.y*p[ti.y*96] + w.z*p[ti.z*96] + w.w*p[ti.w*96];
    }
    __syncthreads();
    __nv_bfloat16* dst = which ? g_refb : g_featb;
    #pragma unroll
    for (int i = 0; i < 4; i++) {
        int nn = blockIdx.x * 32 + threadIdx.y + i * 8;
        dst[(size_t)nn * CDIM + blockIdx.y * 32 + threadIdx.x] =
            __float2bfloat16(t[threadIdx.x][threadIdx.y + i * 8]);
    }
}

// ---------------- bf16 mma.sync GEMM + exp + row sums -----------------------
// C[128x128] tile: 8 warps (4 m x 2 n), warp = 32x64, mma m16n8k16.
// smem rows padded to 40 bf16 (80B) -> 20-bank skew, ldmatrix conflict-free.
#define SROW 40

__global__ __launch_bounds__(256) void k_gemm() {
    int count = g_count;
    int m0 = blockIdx.y * 128;
    if (m0 >= count) return;
    int n0 = blockIdx.x * 128;

    __shared__ __align__(16) __nv_bfloat16 sA[2][128 * SROW];
    __shared__ __align__(16) __nv_bfloat16 sB[2][128 * SROW];
    __shared__ int   s_act[128];
    __shared__ float s_rows[2][128];

    int tid = threadIdx.x, lane = tid & 31, wid = tid >> 5;
    int wm = wid & 3, wn = wid >> 2;

    if (tid < 128)
        s_act[tid] = (m0 + tid < count) ? g_active[m0 + tid] : -1;
    __syncthreads();

    // --- async load of one K-chunk (32 bf16/row) into stage stg ------------
    auto issue = [&](int it, int stg) {
        int k0 = it * 32;
        uint32_t aBase = smem_u32(&sA[stg][0]);
        uint32_t bBase = smem_u32(&sB[stg][0]);
        #pragma unroll
        for (int p = 0; p < 2; p++) {
            int id  = tid + p * 256;         // 0..511
            int row = id >> 2, c = id & 3;
            uint32_t so = (uint32_t)(row * SROW + c * 8) * 2u;
            int ga = s_act[row];
            const void* srcA = g_refb + (size_t)max(ga, 0) * CDIM + k0 + c * 8;
            cpa16(aBase + so, srcA, ga >= 0 ? 16 : 0);
            const void* srcB = g_featb + (size_t)(n0 + row) * CDIM + k0 + c * 8;
            cpa16(bBase + so, srcB, 16);
        }
    };

    issue(0, 0); CP_COMMIT();
    issue(1, 1); CP_COMMIT();

    float d[2][8][4] = {};

    for (int it = 0; it < NIT; it++) {
        int stg = it & 1;
        if (it < NIT - 1) CP_WAIT(1); else CP_WAIT(0);
        __syncthreads();

        uint32_t aBase = smem_u32(&sA[stg][0]);
        uint32_t bBase = smem_u32(&sB[stg][0]);
        #pragma unroll
        for (int k16 = 0; k16 < 2; k16++) {
            uint32_t a[2][4];
            #pragma unroll
            for (int sub = 0; sub < 2; sub++) {
                int row = wm * 32 + sub * 16 + (lane & 7) + ((lane >> 3) & 1) * 8;
                int kOف = k16 * 16 + (lane >> 4) * 8;
                ldsm4(a[sub], aBase + (uint32_t)(row * SROW + kOف) * 2u);
            }
            uint32_t b[4][4];
            #pragma unroll
            for (int bt = 0; bt < 4; bt++) {
                int grp  = lane >> 3;
                int row  = wn * 64 + bt * 16 + (grp >> 1) * 8 + (lane & 7);
                int kOff = k16 * 16 + (grp & 1) * 8;
                ldsm4(b[bt], bBase + (uint32_t)(row * SROW + kOff) * 2u);
            }
            #pragma unroll
            for (int sub = 0; sub < 2; sub++)
                #pragma unroll
                for (int nt = 0; nt < 8; nt++)
                    mma16816(d[sub][nt], a[sub], &b[nt >> 1][(nt & 1) * 2]);
        }
        __syncthreads();
        if (it + 2 < NIT) { issue(it + 2, stg); CP_COMMIT(); }
    }

    // --- epilogue: exp, bf16 store of E, deterministic row sums ------------
    int g  = lane >> 2;            // row group within m16
    int lc = lane & 3;             // col pair
    float rsum[2][2] = {};
    #pragma unroll
    for (int sub = 0; sub < 2; sub++) {
        int rA = m0 + wm * 32 + sub * 16 + g;
        int rB = rA + 8;
        bool vA = (rA < count), vB = (rB < count);
        #pragma unroll
        for (int nt = 0; nt < 8; nt++) {
            int col = n0 + wn * 64 + nt * 8 + lc * 2;
            float e0 = __expf(d[sub][nt][0] * 1e-3f);
            float e1 = __expf(d[sub][nt][1] * 1e-3f);
            float e2 = __expf(d[sub][nt][2] * 1e-3f);
            float e3 = __expf(d[sub][nt][3] * 1e-3f);
            rsum[sub][0] += e0 + e1;
            rsum[sub][1] += e2 + e3;
            if (vA) {
                __nv_bfloat162 p = __floats2bfloat162_rn(e0, e1);
                *(uint32_t*)(g_E + (size_t)rA * NA + col) = *(uint32_t*)&p;
            }
            if (vB) {
                __nv_bfloat162 p = __floats2bfloat162_rn(e2, e3);
                *(uint32_t*)(g_E + (size_t)rB * NA + col) = *(uint32_t*)&p;
            }
        }
        // reduce across the 4 lanes sharing each row
        #pragma unroll
        for (int h = 0; h < 2; h++) {
            float v = rsum[sub][h];
            v += __shfl_xor_sync(0xffffffffu, v, 1);
            v += __shfl_xor_sync(0xffffffffu, v, 2);
            rsum[sub][h] = v;
        }
        if (lc == 0) {
            s_rows[wn][wm * 32 + sub * 16 + g]     = rsum[sub][0];
            s_rows[wn][wm * 32 + sub * 16 + g + 8] = rsum[sub][1];
        }
    }
    __syncthreads();
    if (tid < 128) {
        int m = m0 + tid;
        if (m < count)
            g_Zpart[blockIdx.x * NA + m] = s_rows[0][tid] + s_rows[1][tid];
    }
}

__global__ void k_invz() {
    int i = blockIdx.x * blockDim.x + threadIdx.x;
    if (i >= NA || i >= g_count) return;
    float z = 0.f;
    for (int t = 0; t < MT; t++) z += g_Zpart[t * NA + i];
    g_invZ[i] = 1.f / z;
}

// ---------------- column reduction: attn_out_j = sum_i E[i,j]/Z_i ----------
__global__ void k_colreduce() {
    int jj = blockIdx.x * 256 + threadIdx.x;   // bf16x2 pair index, 4608 total
    int s  = blockIdx.y;
    int count = g_count;
    float a0 = 0.f, a1 = 0.f;
    for (int ci = s; ci < count; ci += SSPLIT) {
        __nv_bfloat162 v = ((const __nv_bfloat162*)(g_E + (size_t)ci * NA))[jj];
        float iz = g_invZ[ci];
        a0 += __low2float(v) * iz;
        a1 += __high2float(v) * iz;
    }
    g_partial[s * NA + 2 * jj]     = a0;
    g_partial[s * NA + 2 * jj + 1] = a1;
}

__global__ void k_colfinish(float* __restrict__ maskout) {
    int j = blockIdx.x * blockDim.x + threadIdx.x;
    if (j >= NA) return;
    float a = 0.f;
    for (int s = 0; s < SSPLIT; s++) a += g_partial[s * NA + j];
    maskout[j] = a;
}

// ---------------- bilinear align_corners 96 -> 48 ---------------------------
__global__ void k_x1(const float* __restrict__ mask) {
    int k = blockIdx.x * blockDim.x + threadIdx.x;
    if (k >= HW48) return;
    int yo = k / 48, xo = k % 48;
    const float step = 95.f / 47.f;
    float ys = yo * step, xs = xo * step;
    int y0 = (int)floorf(ys), x0 = (int)floorf(xs);
    int y1 = min(y0 + 1, 95), x1i = min(x0 + 1, 95);
    float wy = ys - (float)y0, wx = xs - (float)x0;
    float a = mask[y0 * 96 + x0],  b = mask[y0 * 96 + x1i];
    float c = mask[y1 * 96 + x0],  d = mask[y1 * 96 + x1i];
    g_x1[k] = (a * (1.f - wx) + b * wx) * (1.f - wy) + (c * (1.f - wx) + d * wx) * wy;
}

__global__ void k_attn(const float* __restrict__ A) {
    __shared__ float red[256];
    int j = blockIdx.x;
    int t = threadIdx.x;
    float acc = 0.f;
    const float* row = A + (size_t)j * HW48;
    for (int k = t; k < HW48; k += 256) acc += g_x1[k] * row[k];
    red[t] = acc;
    __syncthreads();
    for (int s = 128; s; s >>= 1) {
        if (t < s) red[t] += red[t + s];
        __syncthreads();
    }
    if (t == 0) g_out48[j] = red[0];
}

__global__ void k_trimap(float* __restrict__ out) {
    int idx = blockIdx.x * blockDim.x + threadIdx.x;
    if (idx >= 768 * 768) return;
    int ox = idx % 768, oy = idx / 768;
    float sx = (ox + 0.5f) * (1.f / 16.f) - 0.5f;
    float sy = (oy + 0.5f) * (1.f / 16.f) - 0.5f;
    int x0 = (int)floorf(sx), y0 = (int)floorf(sy);
    float wx = sx - (float)x0, wy = sy - (float)y0;
    int x0c = max(x0, 0), x1c = min(x0 + 1, 47);
    int y0c = max(y0, 0), y1c = min(y0 + 1, 47);
    float a = g_out48[y0c * 48 + x0c], b = g_out48[y0c * 48 + x1c];
    float c = g_out48[y1c * 48 + x0c], d = g_out48[y1c * 48 + x1c];
    out[idx] = (a * (1.f - wx) + b * wx) * (1.f - wy) + (c * (1.f - wx) + d * wx) * wy;
}

// ---------------- launch ----------------------------------------------------
extern "C" void kernel_launch(void* const* d_in, const int* in_sizes, int n_in,
                              void* d_out, int out_size) {
    (void)in_sizes; (void)n_in; (void)out_size;
    const float* ref_img = (const float*)d_in[0];
    const float* ft_cor  = (const float*)d_in[1];
    const float* attnA   = (const float*)d_in[2];
    const float* ft_mat  = (const float*)d_in[3];
    const float* guid    = (const float*)d_in[4];

    float* out     = (float*)d_out;
    float* trimap  = out;                       // 768*768
    float* matting = out + 768 * 768;           // 1280*64*64
    float* maskout = matting + 1280 * 64 * 64;  // 9216

    k_flag<<<36, 256>>>(guid);
    k_compact<<<1, 256>>>();
    k_weights<<<1, 96>>>();

    int nrh = (CDIM * 64 * 96 + 255) / 256;
    dim3 tgrid(NA / 32, CDIM / 32), tblk(32, 8);
    k_resize_h<<<nrh, 256>>>(ft_cor);
    k_resize_vt<<<tgrid, tblk>>>(0);            // -> g_featb
    k_resize_h<<<nrh, 256>>>(ref_img);
    k_resize_vt<<<tgrid, tblk>>>(1);            // -> g_refb

    k_gemm<<<dim3(MT, MT), 256>>>();

    k_invz<<<36, 256>>>();
    k_colreduce<<<dim3(18, SSPLIT), 256>>>();
    k_colfinish<<<36, 256>>>(maskout);

    k_x1<<<9, 256>>>(maskout);
    k_attn<<<HW48, 256>>>(attnA);
    k_trimap<<<(768 * 768 + 255) / 256, 256>>>(trimap);

    cudaMemcpyAsync(matting, ft_mat, (size_t)1280 * 64 * 64 * sizeof(float),
                    cudaMemcpyDeviceToDevice);
}

// round 4
// speedup vs baseline: 5.8137x; 1.0122x over previous
#include <cuda_runtime.h>
#include <cuda_bf16.h>
#include <math.h>
#include <stdint.h>

#define NA     9216      // 96*96
#define CDIM   1280
#define HW48   2304      // 48*48
#define MT     72        // 9216/128 tiles per GEMM dim
#define NIT    40        // 1280/32 K-iterations
#define SSPLIT 64
#define SROW   40        // smem row stride (bf16) -> conflict-free ldmatrix

// ---------------- scratch (device globals; no allocation allowed) ----------
__device__ float g_tmp[2][CDIM * 64 * 96];           // horizontal-resize temps
__device__ __nv_bfloat16 g_refb[(size_t)NA * CDIM];  // (N, C) row-major bf16
__device__ __nv_bfloat16 g_featb[(size_t)NA * CDIM];
__device__ __nv_bfloat16 g_E[(size_t)NA * NA];       // exp(sim), bf16, 170MB
__device__ float g_Zpart[MT * NA];
__device__ float g_invZ[NA];
__device__ float g_partial[SSPLIT * NA];
__device__ float g_x1[HW48];
__device__ float g_out48[HW48];
__device__ int   g_active[NA];
__device__ int   g_count;
__device__ unsigned char g_flag[NA];
__device__ int4   g_it4[96];
__device__ float4 g_wt4[96];

// ---------------- PTX helpers (baseline features only) ---------------------
__device__ __forceinline__ uint32_t smem_u32(const void* p) {
    uint32_t a;
    asm("{ .reg .u64 t; cvta.to.shared.u64 t, %1; cvt.u32.u64 %0, t; }"
        : "=r"(a) : "l"(p));
    return a;
}
__device__ __forceinline__ void cpa16(uint32_t dst, const void* src, int sz) {
    asm volatile("cp.async.cg.shared.global [%0], [%1], 16, %2;"
                 :: "r"(dst), "l"(src), "r"(sz) : "memory");
}
#define CP_COMMIT() asm volatile("cp.async.commit_group;" ::: "memory")
#define CP_WAIT(n)  asm volatile("cp.async.wait_group %0;" :: "n"(n) : "memory")

__device__ __forceinline__ void ldsm4(uint32_t* r, uint32_t addr) {
    asm volatile("ldmatrix.sync.aligned.m8n8.x4.shared.b16 {%0,%1,%2,%3}, [%4];"
                 : "=r"(r[0]), "=r"(r[1]), "=r"(r[2]), "=r"(r[3]) : "r"(addr));
}
__device__ __forceinline__ void mma16816(float* d, const uint32_t* a,
                                         const uint32_t* b) {
    asm volatile(
        "mma.sync.aligned.m16n8k16.row.col.f32.bf16.bf16.f32 "
        "{%0,%1,%2,%3},{%4,%5,%6,%7},{%8,%9},{%0,%1,%2,%3};"
        : "+f"(d[0]), "+f"(d[1]), "+f"(d[2]), "+f"(d[3])
        : "r"(a[0]), "r"(a[1]), "r"(a[2]), "r"(a[3]), "r"(b[0]), "r"(b[1]));
}

// packed f32x2 (base sm_100+ PTX feature)
typedef unsigned long long ull;
__device__ __forceinline__ ull pk2(float lo, float hi) {
    ull r; asm("mov.b64 %0, {%1,%2};" : "=l"(r) : "f"(lo), "f"(hi)); return r;
}
__device__ __forceinline__ void upk2(float& lo, float& hi, ull v) {
    asm("mov.b64 {%0,%1}, %2;" : "=f"(lo), "=f"(hi) : "l"(v));
}
__device__ __forceinline__ ull fma2(ull a, ull b, ull c) {
    ull r; asm("fma.rn.f32x2 %0, %1, %2, %3;" : "=l"(r) : "l"(a), "l"(b), "l"(c));
    return r;
}
__device__ __forceinline__ ull mul2(ull a, ull b) {
    ull r; asm("mul.rn.f32x2 %0, %1, %2;" : "=l"(r) : "l"(a), "l"(b)); return r;
}
__device__ __forceinline__ ull add2(ull a, ull b) {
    ull r; asm("add.rn.f32x2 %0, %1, %2;" : "=l"(r) : "l"(a), "l"(b)); return r;
}

// ---------------- mask + compaction ----------------------------------------
__global__ void k_flag(const float* __restrict__ guid) {
    int i = blockIdx.x * blockDim.x + threadIdx.x;
    if (i >= NA) return;
    int by = i / 96, bx = i % 96;
    const float* p = guid + (by * 8) * 768 + bx * 8;
    bool all = true;
    #pragma unroll
    for (int dy = 0; dy < 8; dy++)
        #pragma unroll
        for (int dx = 0; dx < 8; dx++)
            all = all && (p[dy * 768 + dx] > 0.5f);
    g_flag[i] = all ? 1 : 0;
}

__global__ void k_compact() {
    __shared__ int s_cnt[256];
    __shared__ int s_off[256];
    int t = threadIdx.x;
    int c = 0;
    for (int k = 0; k < 36; k++) c += g_flag[t * 36 + k];
    s_cnt[t] = c;
    __syncthreads();
    if (t == 0) {
        int acc = 0;
        for (int i = 0; i < 256; i++) { s_off[i] = acc; acc += s_cnt[i]; }
        g_count = acc;
    }
    __syncthreads();
    int off = s_off[t];
    for (int k = 0; k < 36; k++) {
        int i = t * 36 + k;
        if (g_flag[i]) g_active[off++] = i;
    }
}

// ---------------- cubic weight tables ---------------------------------------
__device__ __forceinline__ float keys_cubic(float x) {
    x = fabsf(x);
    if (x < 1.f)  return ((1.5f * x - 2.5f) * x) * x + 1.f;
    if (x < 2.f)  return ((-0.5f * x + 2.5f) * x - 4.f) * x + 2.f;
    return 0.f;
}

__global__ void k_weights() {
    int o = threadIdx.x;
    if (o >= 96) return;
    float s = (o + 0.5f) * (64.f / 96.f) - 0.5f;
    int fl = (int)floorf(s);
    int idx[4]; float w[4]; float tot = 0.f;
    #pragma unroll
    for (int t = 0; t < 4; t++) {
        int ii = fl - 1 + t;
        float ww = (ii >= 0 && ii < 64) ? keys_cubic(s - (float)ii) : 0.f;
        idx[t] = min(max(ii, 0), 63);
        w[t] = ww;
        tot += ww;
    }
    float inv = 1.f / tot;
    g_it4[o] = make_int4(idx[0], idx[1], idx[2], idx[3]);
    g_wt4[o] = make_float4(w[0]*inv, w[1]*inv, w[2]*inv, w[3]*inv);
}

// horizontal cubic for both tensors: z=0 ft_cor, z=1 ref
__global__ void k_resize_h2(const float* __restrict__ in0,
                            const float* __restrict__ in1) {
    int idx = blockIdx.x * blockDim.x + threadIdx.x;
    if (idx >= CDIM * 64 * 96) return;
    const float* in = blockIdx.z ? in1 : in0;
    int xo = idx % 96;
    int r  = idx / 96;
    int4  ti = g_it4[xo];
    float4 w = g_wt4[xo];
    const float* p = in + r * 64;
    g_tmp[blockIdx.z][idx] = w.x*p[ti.x] + w.y*p[ti.y] + w.z*p[ti.z] + w.w*p[ti.w];
}

// vertical cubic + transpose to (N, C) bf16; z=0 -> feat, z=1 -> ref
__global__ void k_resize_vt2() {
    __shared__ float t[32][33];
    int z = blockIdx.z;
    int n = blockIdx.x * 32 + threadIdx.x;
    int yo = n / 96, xo = n % 96;
    int4  ti = g_it4[yo];
    float4 w = g_wt4[yo];
    const float* base = g_tmp[z];
    #pragma unroll
    for (int i = 0; i < 4; i++) {
        int c = blockIdx.y * 32 + threadIdx.y + i * 8;
        const float* p = base + c * (64 * 96) + xo;
        t[threadIdx.y + i * 8][threadIdx.x] =
            w.x*p[ti.x*96] + w.y*p[ti.y*96] + w.z*p[ti.z*96] + w.w*p[ti.w*96];
    }
    __syncthreads();
    __nv_bfloat16* dst = z ? g_refb : g_featb;
    #pragma unroll
    for (int i = 0; i < 4; i++) {
        int nn = blockIdx.x * 32 + threadIdx.y + i * 8;
        dst[(size_t)nn * CDIM + blockIdx.y * 32 + threadIdx.x] =
            __float2bfloat16(t[threadIdx.x][threadIdx.y + i * 8]);
    }
}

// ---------------- bf16 mma.sync GEMM + poly-exp + row sums ------------------
// C[128x128] tile: 8 warps (4m x 2n). 3-stage cp.async pipeline, 1 sync/iter.
__global__ __launch_bounds__(256, 2) void k_gemm() {
    int count = g_count;
    int m0 = blockIdx.y * 128;
    if (m0 >= count) return;
    int n0 = blockIdx.x * 128;

    extern __shared__ __align__(16) char dyn[];
    __nv_bfloat16* sA = (__nv_bfloat16*)dyn;                      // 3 stages
    __nv_bfloat16* sB = (__nv_bfloat16*)(dyn + 3 * 128 * SROW * 2);
    __shared__ int   s_act[128];
    __shared__ float s_rows[2][128];

    int tid = threadIdx.x, lane = tid & 31, wid = tid >> 5;
    int wm = wid & 3, wn = wid >> 2;

    if (tid < 128)
        s_act[tid] = (m0 + tid < count) ? g_active[m0 + tid] : -1;
    __syncthreads();

    // per-thread load coords (2 rows for A, 2 for B, 16B each)
    int row0 = tid >> 2,        c0 = tid & 3;
    int row1 = (tid + 256) >> 2, c1 = (tid + 256) & 3;
    int ga0 = s_act[row0], ga1 = s_act[row1];
    const __nv_bfloat16* a0 = g_refb + (size_t)max(ga0, 0) * CDIM + c0 * 8;
    const __nv_bfloat16* a1 = g_refb + (size_t)max(ga1, 0) * CDIM + c1 * 8;
    const __nv_bfloat16* b0 = g_featb + (size_t)(n0 + row0) * CDIM + c0 * 8;
    const __nv_bfloat16* b1 = g_featb + (size_t)(n0 + row1) * CDIM + c1 * 8;
    uint32_t so0 = (uint32_t)(row0 * SROW + c0 * 8) * 2u;
    uint32_t so1 = (uint32_t)(row1 * SROW + c1 * 8) * 2u;

    auto issue = [&](int it, int stg) {
        int k0 = it * 32;
        uint32_t aB = smem_u32(sA + stg * 128 * SROW);
        uint32_t bB = smem_u32(sB + stg * 128 * SROW);
        cpa16(aB + so0, a0 + k0, ga0 >= 0 ? 16 : 0);
        cpa16(bB + so0, b0 + k0, 16);
        cpa16(aB + so1, a1 + k0, ga1 >= 0 ? 16 : 0);
        cpa16(bB + so1, b1 + k0, 16);
    };

    issue(0, 0); CP_COMMIT();
    issue(1, 1); CP_COMMIT();

    float d[2][8][4] = {};

    for (int it = 0; it < NIT; it++) {
        int stg = it - (it / 3) * 3;
        if (it < NIT - 1) CP_WAIT(1); else CP_WAIT(0);
        __syncthreads();

        if (it + 2 < NIT) {
            int ns = (it + 2) - ((it + 2) / 3) * 3;
            issue(it + 2, ns);
            CP_COMMIT();
        }

        uint32_t aBase = smem_u32(sA + stg * 128 * SROW);
        uint32_t bBase = smem_u32(sB + stg * 128 * SROW);
        #pragma unroll
        for (int k16 = 0; k16 < 2; k16++) {
            uint32_t a[2][4];
            #pragma unroll
            for (int sub = 0; sub < 2; sub++) {
                int row = wm * 32 + sub * 16 + (lane & 7) + ((lane >> 3) & 1) * 8;
                int ko  = k16 * 16 + (lane >> 4) * 8;
                ldsm4(a[sub], aBase + (uint32_t)(row * SROW + ko) * 2u);
            }
            uint32_t b[4][4];
            #pragma unroll
            for (int bt = 0; bt < 4; bt++) {
                int grp = lane >> 3;
                int row = wn * 64 + bt * 16 + (grp >> 1) * 8 + (lane & 7);
                int ko  = k16 * 16 + (grp & 1) * 8;
                ldsm4(b[bt], bBase + (uint32_t)(row * SROW + ko) * 2u);
            }
            #pragma unroll
            for (int sub = 0; sub < 2; sub++)
                #pragma unroll
                for (int nt = 0; nt < 8; nt++)
                    mma16816(d[sub][nt], a[sub], &b[nt >> 1][(nt & 1) * 2]);
        }
    }

    // --- epilogue: packed f32x2 order-4 poly exp, bf16 E, row sums ----------
    const ull SC  = pk2(1e-3f, 1e-3f);
    const ull C24 = pk2(1.f/24.f, 1.f/24.f);
    const ull C6  = pk2(1.f/6.f, 1.f/6.f);
    const ull CH  = pk2(0.5f, 0.5f);
    const ull C1  = pk2(1.f, 1.f);

    int g  = lane >> 2;
    int lc = lane & 3;
    #pragma unroll
    for (int sub = 0; sub < 2; sub++) {
        int rA = m0 + wm * 32 + sub * 16 + g;
        int rB = rA + 8;
        bool vA = (rA < count), vB = (rB < count);
        ull rsA = 0ull, rsB = 0ull;          // packed (0.f, 0.f)
        #pragma unroll
        for (int nt = 0; nt < 8; nt++) {
            int col = n0 + wn * 64 + nt * 8 + lc * 2;
            ull xA = mul2(pk2(d[sub][nt][0], d[sub][nt][1]), SC);
            ull tA = fma2(xA, C24, C6);
            tA = fma2(xA, tA, CH);
            tA = fma2(xA, tA, C1);
            ull eA = fma2(xA, tA, C1);
            rsA = add2(rsA, eA);
            ull xB = mul2(pk2(d[sub][nt][2], d[sub][nt][3]), SC);
            ull tB = fma2(xB, C24, C6);
            tB = fma2(xB, tB, CH);
            tB = fma2(xB, tB, C1);
            ull eB = fma2(xB, tB, C1);
            rsB = add2(rsB, eB);
            if (vA) {
                float e0, e1; upk2(e0, e1, eA);
                __nv_bfloat162 p = __floats2bfloat162_rn(e0, e1);
                *(uint32_t*)(g_E + (size_t)rA * NA + col) = *(uint32_t*)&p;
            }
            if (vB) {
                float e2, e3; upk2(e2, e3, eB);
                __nv_bfloat162 p = __floats2bfloat162_rn(e2, e3);
                *(uint32_t*)(g_E + (size_t)rB * NA + col) = *(uint32_t*)&p;
            }
        }
        float a0f, a1f, b0f, b1f;
        upk2(a0f, a1f, rsA);
        upk2(b0f, b1f, rsB);
        float sA2 = a0f + a1f, sB2 = b0f + b1f;
        sA2 += __shfl_xor_sync(0xffffffffu, sA2, 1);
        sA2 += __shfl_xor_sync(0xffffffffu, sA2, 2);
        sB2 += __shfl_xor_sync(0xffffffffu, sB2, 1);
        sB2 += __shfl_xor_sync(0xffffffffu, sB2, 2);
        if (lc == 0) {
            s_rows[wn][wm * 32 + sub * 16 + g]     = sA2;
            s_rows[wn][wm * 32 + sub * 16 + g + 8] = sB2;
        }
    }
    __syncthreads();
    if (tid < 128) {
        int m = m0 + tid;
        if (m < count)
            g_Zpart[blockIdx.x * NA + m] = s_rows[0][tid] + s_rows[1][tid];
    }
}

__global__ void k_invz() {
    int i = blockIdx.x * blockDim.x + threadIdx.x;
    if (i >= NA || i >= g_count) return;
    float z = 0.f;
    for (int t = 0; t < MT; t++) z += g_Zpart[t * NA + i];
    g_invZ[i] = 1.f / z;
}

// ---------------- column reduction: attn_out_j = sum_i E[i,j]/Z_i ----------
__global__ void k_colreduce() {
    int jj = blockIdx.x * 256 + threadIdx.x;   // bf16x2 pair index
    int s  = blockIdx.y;
    int count = g_count;
    float a0 = 0.f, a1 = 0.f;
    for (int ci = s; ci < count; ci += SSPLIT) {
        __nv_bfloat162 v = ((const __nv_bfloat162*)(g_E + (size_t)ci * NA))[jj];
        float iz = g_invZ[ci];
        a0 += __low2float(v) * iz;
        a1 += __high2float(v) * iz;
    }
    g_partial[s * NA + 2 * jj]     = a0;
    g_partial[s * NA + 2 * jj + 1] = a1;
}

__global__ void k_colfinish(float* __restrict__ maskout) {
    int j = blockIdx.x * blockDim.x + threadIdx.x;
    if (j >= NA) return;
    float a = 0.f;
    for (int s = 0; s < SSPLIT; s++) a += g_partial[s * NA + j];
    maskout[j] = a;
}

// ---------------- bilinear align_corners 96 -> 48 ---------------------------
__global__ void k_x1(const float* __restrict__ mask) {
    int k = blockIdx.x * blockDim.x + threadIdx.x;
    if (k >= HW48) return;
    int yo = k / 48, xo = k % 48;
    const float step = 95.f / 47.f;
    float ys = yo * step, xs = xo * step;
    int y0 = (int)floorf(ys), x0 = (int)floorf(xs);
    int y1 = min(y0 + 1, 95), x1i = min(x0 + 1, 95);
    float wy = ys - (float)y0, wx = xs - (float)x0;
    float a = mask[y0 * 96 + x0],  b = mask[y0 * 96 + x1i];
    float c = mask[y1 * 96 + x0],  d = mask[y1 * 96 + x1i];
    g_x1[k] = (a * (1.f - wx) + b * wx) * (1.f - wy) + (c * (1.f - wx) + d * wx) * wy;
}

__global__ void k_attn(const float* __restrict__ A) {
    __shared__ float red[256];
    int j = blockIdx.x;
    int t = threadIdx.x;
    float acc = 0.f;
    const float* row = A + (size_t)j * HW48;
    for (int k = t; k < HW48; k += 256) acc += g_x1[k] * row[k];
    red[t] = acc;
    __syncthreads();
    for (int s = 128; s; s >>= 1) {
        if (t < s) red[t] += red[t + s];
        __syncthreads();
    }
    if (t == 0) g_out48[j] = red[0];
}

__global__ void k_trimap(float* __restrict__ out) {
    int idx = blockIdx.x * blockDim.x + threadIdx.x;
    if (idx >= 768 * 768) return;
    int ox = idx % 768, oy = idx / 768;
    float sx = (ox + 0.5f) * (1.f / 16.f) - 0.5f;
    float sy = (oy + 0.5f) * (1.f / 16.f) - 0.5f;
    int x0 = (int)floorf(sx), y0 = (int)floorf(sy);
    float wx = sx - (float)x0, wy = sy - (float)y0;
    int x0c = max(x0, 0), x1c = min(x0 + 1, 47);
    int y0c = max(y0, 0), y1c = min(y0 + 1, 47);
    float a = g_out48[y0c * 48 + x0c], b = g_out48[y0c * 48 + x1c];
    float c = g_out48[y1c * 48 + x0c], d = g_out48[y1c * 48 + x1c];
    out[idx] = (a * (1.f - wx) + b * wx) * (1.f - wy) + (c * (1.f - wx) + d * wx) * wy;
}

// ---------------- launch ----------------------------------------------------
extern "C" void kernel_launch(void* const* d_in, const int* in_sizes, int n_in,
                              void* d_out, int out_size) {
    (void)in_sizes; (void)n_in; (void)out_size;
    const float* ref_img = (const float*)d_in[0];
    const float* ft_cor  = (const float*)d_in[1];
    const float* attnA   = (const float*)d_in[2];
    const float* ft_mat  = (const float*)d_in[3];
    const float* guid    = (const float*)d_in[4];

    float* out     = (float*)d_out;
    float* trimap  = out;                       // 768*768
    float* matting = out + 768 * 768;           // 1280*64*64
    float* maskout = matting + 1280 * 64 * 64;  // 9216

    k_flag<<<36, 256>>>(guid);
    k_compact<<<1, 256>>>();
    k_weights<<<1, 96>>>();

    int nrh = (CDIM * 64 * 96 + 255) / 256;
    k_resize_h2<<<dim3(nrh, 1, 2), 256>>>(ft_cor, ref_img);
    k_resize_vt2<<<dim3(NA / 32, CDIM / 32, 2), dim3(32, 8)>>>();

    const int GEMM_SMEM = 3 * 128 * SROW * 2 * 2;   // 61440
    cudaFuncSetAttribute(k_gemm, cudaFuncAttributeMaxDynamicSharedMemorySize,
                         GEMM_SMEM);
    k_gemm<<<dim3(MT, MT), 256, GEMM_SMEM>>>();

    k_invz<<<36, 256>>>();
    k_colreduce<<<dim3(18, SSPLIT), 256>>>();
    k_colfinish<<<36, 256>>>(maskout);

    k_x1<<<9, 256>>>(maskout);
    k_attn<<<HW48, 256>>>(attnA);
    k_trimap<<<(768 * 768 + 255) / 256, 256>>>(trimap);

    cudaMemcpyAsync(matting, ft_mat, (size_t)1280 * 64 * 64 * sizeof(float),
                    cudaMemcpyDeviceToDevice);
}